// round 1
// baseline (speedup 1.0000x reference)
#include <cuda_runtime.h>

#define B_   256
#define T_   512
#define DIN  128
#define H_   512
#define DOUT 64

// Scratch (allocation-free rule: __device__ globals)
__device__ float g_xproj[(size_t)B_ * T_ * H_];  // [b][t][h]  = inputs@Win + brec
__device__ float g_hall [(size_t)B_ * T_ * H_];  // [b][t][h]  = h_t for all t

// Packed fp32x2 FMA (Blackwell FFMA2): 2x fp32 FMA throughput vs FFMA-3reg.
union F2U { float2 f; unsigned long long u; };
__device__ __forceinline__ float2 ffma2(float2 a, float2 b, float2 c) {
    F2U A, Bv, C, D;
    A.f = a; Bv.f = b; C.f = c;
    asm("fma.rn.f32x2 %0, %1, %2, %3;" : "=l"(D.u) : "l"(A.u), "l"(Bv.u), "l"(C.u));
    return D.f;
}

// ---------------------------------------------------------------------------
// Kernel A: xproj[b][t][h] = inputs[b][t][:] @ Win[:,h] + brec[h]
// Tile: 32 rows x 512 cols per block; thread = 1 col-pair x 32 rows.
// ---------------------------------------------------------------------------
__global__ void __launch_bounds__(256, 1) rnn_xproj(
    const float* __restrict__ inputs,
    const float* __restrict__ Win,
    const float* __restrict__ brec)
{
    __shared__ __align__(16) float2 x_dup[32][DIN];  // {x,x} duplicated, 32KB
    const int tid = threadIdx.x;
    const size_t r0 = (size_t)blockIdx.x * 32;  // row = b*T + t

    for (int i = tid; i < 32 * DIN; i += 256) {
        int r = i >> 7, k = i & (DIN - 1);
        float v = inputs[(r0 + r) * DIN + k];
        x_dup[r][k] = make_float2(v, v);
    }
    __syncthreads();

    const float2* __restrict__ W2 = reinterpret_cast<const float2*>(Win);  // [k][256]
    float2 acc[32];
#pragma unroll
    for (int r = 0; r < 32; r++) acc[r] = make_float2(0.f, 0.f);

#pragma unroll 2
    for (int k = 0; k < DIN; k += 2) {
        float2 w0 = W2[(size_t)k * (H_ / 2) + tid];
        float2 w1 = W2[(size_t)(k + 1) * (H_ / 2) + tid];
#pragma unroll
        for (int r = 0; r < 32; r++) {
            float4 hx = *reinterpret_cast<const float4*>(&x_dup[r][k]);
            acc[r] = ffma2(make_float2(hx.x, hx.y), w0, acc[r]);
            acc[r] = ffma2(make_float2(hx.z, hx.w), w1, acc[r]);
        }
    }

    float2 bb = reinterpret_cast<const float2*>(brec)[tid];
    float2* __restrict__ out2 = reinterpret_cast<float2*>(g_xproj);
#pragma unroll
    for (int r = 0; r < 32; r++)
        out2[(r0 + r) * (H_ / 2) + tid] = make_float2(acc[r].x + bb.x, acc[r].y + bb.y);
}

// ---------------------------------------------------------------------------
// Kernel B: sequential recurrence. 64 independent CTAs, each owns 4 batch
// rows for all 512 steps (no inter-CTA sync). h kept in SMEM as duplicated
// {h,h} float2 pairs so the inner loop is pure LDS.128 + LDG.64 + FFMA2.
// Per step: h_new = tanh(h @ Wrec + xproj[:,t,:]); h_new -> g_hall.
// ---------------------------------------------------------------------------
__global__ void __launch_bounds__(256, 1) rnn_recurrent(
    const float* __restrict__ Wrec,
    const float* __restrict__ h0)
{
    __shared__ __align__(16) float2 h_dup[2][4][H_];  // double-buffered, 32KB
    const int tid = threadIdx.x;
    const int b0 = blockIdx.x * 4;

    // init h = h0 (broadcast across the 4 batch rows)
    for (int i = tid; i < H_; i += 256) {
        float v = h0[i];
        float2 vv = make_float2(v, v);
#pragma unroll
        for (int b = 0; b < 4; b++) h_dup[0][b][i] = vv;
    }
    __syncthreads();

    const float2* __restrict__ W2 = reinterpret_cast<const float2*>(Wrec);  // [k][256]
    const float2* __restrict__ xp2 = reinterpret_cast<const float2*>(g_xproj);
    float2* __restrict__ hall2 = reinterpret_cast<float2*>(g_hall);

    int p = 0;
    for (int t = 0; t < T_; t++) {
        // Issue xproj loads early; consumed only after the GEMM (latency hidden)
        float2 xp[4];
#pragma unroll
        for (int b = 0; b < 4; b++)
            xp[b] = xp2[((size_t)(b0 + b) * T_ + t) * (H_ / 2) + tid];

        float2 acc[4];
#pragma unroll
        for (int b = 0; b < 4; b++) acc[b] = make_float2(0.f, 0.f);

#pragma unroll 4
        for (int k = 0; k < H_; k += 2) {
            float2 w0 = W2[(size_t)k * (H_ / 2) + tid];
            float2 w1 = W2[(size_t)(k + 1) * (H_ / 2) + tid];
#pragma unroll
            for (int b = 0; b < 4; b++) {
                float4 hx = *reinterpret_cast<const float4*>(&h_dup[p][b][k]);
                acc[b] = ffma2(make_float2(hx.x, hx.y), w0, acc[b]);
                acc[b] = ffma2(make_float2(hx.z, hx.w), w1, acc[b]);
            }
        }

#pragma unroll
        for (int b = 0; b < 4; b++) {
            float y0 = tanhf(acc[b].x + xp[b].x);
            float y1 = tanhf(acc[b].y + xp[b].y);
            hall2[((size_t)(b0 + b) * T_ + t) * (H_ / 2) + tid] = make_float2(y0, y1);
            h_dup[p ^ 1][b][2 * tid]     = make_float2(y0, y0);
            h_dup[p ^ 1][b][2 * tid + 1] = make_float2(y1, y1);
        }
        __syncthreads();
        p ^= 1;
    }
}

// ---------------------------------------------------------------------------
// Kernel C: out[r][d] = g_hall[r][:] @ Wout[:,d] + bout[d]
// Tile: 64 rows x 64 cols; thread = 8 rows x 1 col-pair; K streamed in 64-chunks.
// ---------------------------------------------------------------------------
__global__ void __launch_bounds__(256, 1) rnn_outproj(
    const float* __restrict__ Wout,
    const float* __restrict__ bout,
    float* __restrict__ out)
{
    __shared__ __align__(16) float2 hd[64][64];  // {h,h} duplicated tile, 32KB
    const int tid = threadIdx.x;
    const int pair = tid & 31;   // col pair: cols 2*pair, 2*pair+1
    const int rg = tid >> 5;     // row group 0..7 (8 rows each)
    const size_t r0 = (size_t)blockIdx.x * 64;

    float2 acc[8];
#pragma unroll
    for (int i = 0; i < 8; i++) acc[i] = make_float2(0.f, 0.f);

    const float2* __restrict__ Wo2 = reinterpret_cast<const float2*>(Wout);  // [k][32]

    for (int kc = 0; kc < H_; kc += 64) {
        __syncthreads();
        for (int i = tid; i < 64 * 64; i += 256) {
            int r = i >> 6, k = i & 63;
            float v = g_hall[(r0 + r) * H_ + kc + k];
            hd[r][k] = make_float2(v, v);
        }
        __syncthreads();

#pragma unroll 4
        for (int kk = 0; kk < 64; kk += 2) {
            float2 w0 = Wo2[(size_t)(kc + kk) * (DOUT / 2) + pair];
            float2 w1 = Wo2[(size_t)(kc + kk + 1) * (DOUT / 2) + pair];
#pragma unroll
            for (int i = 0; i < 8; i++) {
                int r = rg * 8 + i;
                float4 hx = *reinterpret_cast<const float4*>(&hd[r][kk]);
                acc[i] = ffma2(make_float2(hx.x, hx.y), w0, acc[i]);
                acc[i] = ffma2(make_float2(hx.z, hx.w), w1, acc[i]);
            }
        }
    }

    float2 bb = reinterpret_cast<const float2*>(bout)[pair];
    float2* __restrict__ out2 = reinterpret_cast<float2*>(out);
#pragma unroll
    for (int i = 0; i < 8; i++) {
        int r = rg * 8 + i;
        out2[(r0 + r) * (DOUT / 2) + pair] =
            make_float2(acc[i].x + bb.x, acc[i].y + bb.y);
    }
}

// ---------------------------------------------------------------------------
extern "C" void kernel_launch(void* const* d_in, const int* in_sizes, int n_in,
                              void* d_out, int out_size)
{
    const float* inputs = (const float*)d_in[0];
    const float* Win    = (const float*)d_in[1];
    const float* Wrec   = (const float*)d_in[2];
    const float* brec   = (const float*)d_in[3];
    const float* Wout   = (const float*)d_in[4];
    const float* bout   = (const float*)d_in[5];
    const float* h0     = (const float*)d_in[6];

    rnn_xproj<<<(B_ * T_) / 32, 256>>>(inputs, Win, brec);
    rnn_recurrent<<<B_ / 4, 256>>>(Wrec, h0);
    rnn_outproj<<<(B_ * T_) / 64, 256>>>(Wout, bout, (float*)d_out);
}

// round 2
// speedup vs baseline: 1.0105x; 1.0105x over previous
#include <cuda_runtime.h>

#define B_   256
#define T_   512
#define DIN  128
#define H_   512
#define DOUT 64

// Scratch (allocation-free rule: __device__ globals)
__device__ float g_xproj[(size_t)B_ * T_ * H_];  // [b][t][h]  = inputs@Win + brec
__device__ float g_hall [(size_t)B_ * T_ * H_];  // [b][t][h]  = h_t for all t

// Packed fp32x2 FMA (Blackwell FFMA2): 2x fp32 FMA throughput vs FFMA-3reg.
union F2U { float2 f; unsigned long long u; };
__device__ __forceinline__ float2 ffma2(float2 a, float2 b, float2 c) {
    F2U A, Bv, C, D;
    A.f = a; Bv.f = b; C.f = c;
    asm("fma.rn.f32x2 %0, %1, %2, %3;" : "=l"(D.u) : "l"(A.u), "l"(Bv.u), "l"(C.u));
    return D.f;
}

// ---------------------------------------------------------------------------
// Kernel A: xproj[b][t][h] = inputs[b][t][:] @ Win[:,h] + brec[h]
// Tile: 32 rows x 512 cols per block; thread = 1 col-pair x 32 rows.
// ---------------------------------------------------------------------------
__global__ void __launch_bounds__(256, 1) rnn_xproj(
    const float* __restrict__ inputs,
    const float* __restrict__ Win,
    const float* __restrict__ brec)
{
    __shared__ __align__(16) float2 x_dup[32][DIN];  // {x,x} duplicated, 32KB
    const int tid = threadIdx.x;
    const size_t r0 = (size_t)blockIdx.x * 32;  // row = b*T + t

    for (int i = tid; i < 32 * DIN; i += 256) {
        int r = i >> 7, k = i & (DIN - 1);
        float v = inputs[(r0 + r) * DIN + k];
        x_dup[r][k] = make_float2(v, v);
    }
    __syncthreads();

    const float2* __restrict__ W2 = reinterpret_cast<const float2*>(Win);  // [k][256]
    float2 acc[32];
#pragma unroll
    for (int r = 0; r < 32; r++) acc[r] = make_float2(0.f, 0.f);

#pragma unroll 2
    for (int k = 0; k < DIN; k += 2) {
        float2 w0 = W2[(size_t)k * (H_ / 2) + tid];
        float2 w1 = W2[(size_t)(k + 1) * (H_ / 2) + tid];
#pragma unroll
        for (int r = 0; r < 32; r++) {
            float4 hx = *reinterpret_cast<const float4*>(&x_dup[r][k]);
            acc[r] = ffma2(make_float2(hx.x, hx.y), w0, acc[r]);
            acc[r] = ffma2(make_float2(hx.z, hx.w), w1, acc[r]);
        }
    }

    float2 bb = reinterpret_cast<const float2*>(brec)[tid];
    float2* __restrict__ out2 = reinterpret_cast<float2*>(g_xproj);
#pragma unroll
    for (int r = 0; r < 32; r++)
        out2[(r0 + r) * (H_ / 2) + tid] = make_float2(acc[r].x + bb.x, acc[r].y + bb.y);
}

// ---------------------------------------------------------------------------
// Kernel B: sequential recurrence. 64 independent CTAs, each owns 4 batch
// rows for all 512 steps (no inter-CTA sync). h kept in SMEM as duplicated
// {h,h} float2 pairs so the inner loop is pure LDS.128 + LDG.64 + FFMA2.
// Per step: h_new = tanh(h @ Wrec + xproj[:,t,:]); h_new -> g_hall.
// ---------------------------------------------------------------------------
__global__ void __launch_bounds__(256, 1) rnn_recurrent(
    const float* __restrict__ Wrec,
    const float* __restrict__ h0)
{
    __shared__ __align__(16) float2 h_dup[2][4][H_];  // double-buffered, 32KB
    const int tid = threadIdx.x;
    const int b0 = blockIdx.x * 4;

    // init h = h0 (broadcast across the 4 batch rows)
    for (int i = tid; i < H_; i += 256) {
        float v = h0[i];
        float2 vv = make_float2(v, v);
#pragma unroll
        for (int b = 0; b < 4; b++) h_dup[0][b][i] = vv;
    }
    __syncthreads();

    const float2* __restrict__ W2 = reinterpret_cast<const float2*>(Wrec);  // [k][256]
    const float2* __restrict__ xp2 = reinterpret_cast<const float2*>(g_xproj);
    float2* __restrict__ hall2 = reinterpret_cast<float2*>(g_hall);

    int p = 0;
    for (int t = 0; t < T_; t++) {
        // Issue xproj loads early; consumed only after the GEMM (latency hidden)
        float2 xp[4];
#pragma unroll
        for (int b = 0; b < 4; b++)
            xp[b] = xp2[((size_t)(b0 + b) * T_ + t) * (H_ / 2) + tid];

        float2 acc[4];
#pragma unroll
        for (int b = 0; b < 4; b++) acc[b] = make_float2(0.f, 0.f);

#pragma unroll 4
        for (int k = 0; k < H_; k += 2) {
            float2 w0 = W2[(size_t)k * (H_ / 2) + tid];
            float2 w1 = W2[(size_t)(k + 1) * (H_ / 2) + tid];
#pragma unroll
            for (int b = 0; b < 4; b++) {
                float4 hx = *reinterpret_cast<const float4*>(&h_dup[p][b][k]);
                acc[b] = ffma2(make_float2(hx.x, hx.y), w0, acc[b]);
                acc[b] = ffma2(make_float2(hx.z, hx.w), w1, acc[b]);
            }
        }

#pragma unroll
        for (int b = 0; b < 4; b++) {
            float y0 = tanhf(acc[b].x + xp[b].x);
            float y1 = tanhf(acc[b].y + xp[b].y);
            hall2[((size_t)(b0 + b) * T_ + t) * (H_ / 2) + tid] = make_float2(y0, y1);
            h_dup[p ^ 1][b][2 * tid]     = make_float2(y0, y0);
            h_dup[p ^ 1][b][2 * tid + 1] = make_float2(y1, y1);
        }
        __syncthreads();
        p ^= 1;
    }
}

// ---------------------------------------------------------------------------
// Kernel C: out[r][d] = g_hall[r][:] @ Wout[:,d] + bout[d]
// Tile: 64 rows x 64 cols; thread = 8 rows x 1 col-pair; K streamed in 64-chunks.
// ---------------------------------------------------------------------------
__global__ void __launch_bounds__(256, 1) rnn_outproj(
    const float* __restrict__ Wout,
    const float* __restrict__ bout,
    float* __restrict__ out)
{
    __shared__ __align__(16) float2 hd[64][64];  // {h,h} duplicated tile, 32KB
    const int tid = threadIdx.x;
    const int pair = tid & 31;   // col pair: cols 2*pair, 2*pair+1
    const int rg = tid >> 5;     // row group 0..7 (8 rows each)
    const size_t r0 = (size_t)blockIdx.x * 64;

    float2 acc[8];
#pragma unroll
    for (int i = 0; i < 8; i++) acc[i] = make_float2(0.f, 0.f);

    const float2* __restrict__ Wo2 = reinterpret_cast<const float2*>(Wout);  // [k][32]

    for (int kc = 0; kc < H_; kc += 64) {
        __syncthreads();
        for (int i = tid; i < 64 * 64; i += 256) {
            int r = i >> 6, k = i & 63;
            float v = g_hall[(r0 + r) * H_ + kc + k];
            hd[r][k] = make_float2(v, v);
        }
        __syncthreads();

#pragma unroll 4
        for (int kk = 0; kk < 64; kk += 2) {
            float2 w0 = Wo2[(size_t)(kc + kk) * (DOUT / 2) + pair];
            float2 w1 = Wo2[(size_t)(kc + kk + 1) * (DOUT / 2) + pair];
#pragma unroll
            for (int i = 0; i < 8; i++) {
                int r = rg * 8 + i;
                float4 hx = *reinterpret_cast<const float4*>(&hd[r][kk]);
                acc[i] = ffma2(make_float2(hx.x, hx.y), w0, acc[i]);
                acc[i] = ffma2(make_float2(hx.z, hx.w), w1, acc[i]);
            }
        }
    }

    float2 bb = reinterpret_cast<const float2*>(bout)[pair];
    float2* __restrict__ out2 = reinterpret_cast<float2*>(out);
#pragma unroll
    for (int i = 0; i < 8; i++) {
        int r = rg * 8 + i;
        out2[(r0 + r) * (DOUT / 2) + pair] =
            make_float2(acc[i].x + bb.x, acc[i].y + bb.y);
    }
}

// ---------------------------------------------------------------------------
extern "C" void kernel_launch(void* const* d_in, const int* in_sizes, int n_in,
                              void* d_out, int out_size)
{
    const float* inputs = (const float*)d_in[0];
    const float* Win    = (const float*)d_in[1];
    const float* Wrec   = (const float*)d_in[2];
    const float* brec   = (const float*)d_in[3];
    const float* Wout   = (const float*)d_in[4];
    const float* bout   = (const float*)d_in[5];
    const float* h0     = (const float*)d_in[6];

    rnn_xproj<<<(B_ * T_) / 32, 256>>>(inputs, Win, brec);
    rnn_recurrent<<<B_ / 4, 256>>>(Wrec, h0);
    rnn_outproj<<<(B_ * T_) / 64, 256>>>(Wout, bout, (float*)d_out);
}